// round 4
// baseline (speedup 1.0000x reference)
#include <cuda_runtime.h>
#include <cuda_bf16.h>

// CausalSequenceCML: 16 fused steps of depthwise-causal-conv logistic CML.
// B=4, T=4096, C=512, K=4, STEPS=16.
//
// Round-4: FMA-pipe is saturated at the 3-reg-FFMA rate (rt=2); recover the
// remaining headroom via occupancy + geometry:
//  - SS=12 strips x LL=19 cells (TILE=228, VALID=180, NTILES=23):
//    per-SM work ceil(1472/148)=10 CTAs x 228 = 2280 cell-units (vs 2376).
//  - D = beta*drive moved to smem (thread-private, lane==channel, conflict
//    free) -> ~40 regs -> 4 CTAs/SM, 48 warps (75% occ).
//  - smem zero-pad strip -1 removes the s>0 branch; step loop unrolled x2.

#define Bdim 4
#define Tdim 4096
#define Cdim 512
#define NSTEPS 16
#define CC 32                // channels per block (warp-contiguous)
#define SS 12                // time strips per block
#define LL 19                // cells per thread
#define TILE (SS * LL)       // 228
#define HALO 48              // 3 * NSTEPS
#define VALID (TILE - HALO)  // 180
#define NTILES ((Tdim + VALID - 1) / VALID)  // 23

__global__ void __launch_bounds__(CC * SS, 4)
cml_kernel(const float* __restrict__ drive,
           const float* __restrict__ r,
           const float* __restrict__ eps,
           const float* __restrict__ beta,
           const float* __restrict__ Kc,
           float* __restrict__ out)
{
    // boundary m' values, zero-padded with a phantom strip at index 0:
    // [buf][strip+1][3][channel]
    __shared__ float bm[2][SS + 1][3][CC];
    // step-invariant drive term, thread-private: [strip][cell][channel]
    __shared__ float Dsh[SS][LL][CC];

    const int tid = threadIdx.x;
    const int c   = tid & (CC - 1);
    const int s   = tid >> 5;
    const int cg  = blockIdx.y * CC + c;
    const int b   = blockIdx.z;
    const int gt0 = (int)blockIdx.x * VALID - HALO;
    const int base = b * (Tdim * Cdim);

    // zero-pad phantom strip (both buffers)
    if (s == 0) {
#pragma unroll
        for (int j = 0; j < 3; j++) {
            bm[0][0][j][c] = 0.0f;
            bm[1][0][j][c] = 0.0f;
        }
    }

    // per-channel constants; fold r into the conv weights
    const float rr = r[cg];
    const float ee = eps[cg];
    const float bb = beta[cg];
    const float k0 = Kc[cg * 4 + 0];
    const float k1 = Kc[cg * 4 + 1];
    const float k2 = Kc[cg * 4 + 2];
    const float k3 = Kc[cg * 4 + 3];
    const float onemb = 1.0f - bb;
    const float A  = onemb * (1.0f - ee);
    const float Bc = onemb * ee;
    const float v3 = fmaf(Bc, k3, A) * rr;   // coeff of m'[t]
    const float v2 = Bc * k2 * rr;           // m'[t-1]
    const float v1 = Bc * k1 * rr;           // m'[t-2]
    const float v0 = Bc * k0 * rr;           // m'[t-3]

    // load drive -> g (regs), D = beta*drive (smem, thread-private)
    float g[LL];
#pragma unroll
    for (int i = 0; i < LL; i++) {
        const int gt = gt0 + s * LL + i;
        float d = 0.0f;
        if (gt >= 0 && gt < Tdim)
            d = drive[base + gt * Cdim + cg];
        g[i] = d;
        Dsh[s][i][c] = bb * d;
    }
    // (no sync needed for Dsh: written and read by the same thread;
    //  the step-0 __syncthreads covers the bm phantom-strip zeroing)

#pragma unroll 2
    for (int step = 0; step < NSTEPS; step++) {
        float (*buf)[3][CC] = bm[step & 1];
        // boundary: m' of this strip's last 3 cells -> slot s+1
#pragma unroll
        for (int j = 0; j < 3; j++) {
            const float gi = g[LL - 3 + j];
            buf[s + 1][j][c] = fmaf(-gi, gi, gi);   // g*(1-g)
        }
        __syncthreads();

        float m3 = buf[s][0][c];
        float m2 = buf[s][1][c];
        float m1 = buf[s][2][c];
        // main sweep: 5 FMA ops per cell (m0 dedups to rt=1)
#pragma unroll
        for (int i = 0; i < LL; i++) {
            const float gi = g[i];
            const float m0 = fmaf(-gi, gi, gi);     // g*(1-g)
            float acc = fmaf(v3, m0, Dsh[s][i][c]);
            acc = fmaf(v2, m1, acc);
            acc = fmaf(v1, m2, acc);
            g[i] = fmaf(v0, m3, acc);
            m3 = m2; m2 = m1; m1 = m0;
        }
    }

    // clip + store valid region
#pragma unroll
    for (int i = 0; i < LL; i++) {
        const int lt = s * LL + i;
        const int gt = gt0 + lt;
        if (lt >= HALO && gt < Tdim) {
            float v = fminf(fmaxf(g[i], 1.0e-4f), 1.0f - 1.0e-4f);
            out[base + gt * Cdim + cg] = v;
        }
    }
}

extern "C" void kernel_launch(void* const* d_in, const int* in_sizes, int n_in,
                              void* d_out, int out_size)
{
    const float* drive = (const float*)d_in[0];
    const float* r     = (const float*)d_in[1];
    const float* eps   = (const float*)d_in[2];
    const float* beta  = (const float*)d_in[3];
    const float* Kc    = (const float*)d_in[4];
    float* out = (float*)d_out;

    dim3 grid(NTILES, Cdim / CC, Bdim);   // 23 x 16 x 4
    cml_kernel<<<grid, CC * SS>>>(drive, r, eps, beta, Kc, out);
}

// round 5
// speedup vs baseline: 1.1320x; 1.1320x over previous
#include <cuda_runtime.h>
#include <cuda_bf16.h>

// CausalSequenceCML: 16 fused steps of depthwise-causal-conv logistic CML.
// B=4, T=4096, C=512, K=4, STEPS=16.
//
// Round-5: warp-per-channel layout.
//  - One warp owns one channel and a 576-cell time tile (32 lanes x 18).
//  - Per-step halo exchange = 3x __shfl_up_sync; NO __syncthreads and NO
//    smem traffic inside the 16-step loop.
//  - Halo amp 576/528 = 1.09 (vs 1.286 in R3): -15% total work.
//  - Conv coefficients are warp-uniform -> UR operands -> lower FFMA
//    register-bank pressure (the only lever under the rt=2 FFMA-3reg cap).
//  - Global I/O via an smem transpose stage (coalesced-ish), 3 barriers
//    total outside the hot loop.

#define Bdim 4
#define Tdim 4096
#define Cdim 512
#define NSTEPS 16
#define WC 8                  // channels (warps) per block
#define LL 18                 // cells per lane
#define TILE (32 * LL)        // 576 cells per warp tile
#define HALO 48               // 3 * NSTEPS
#define VALID (TILE - HALO)   // 528
#define NTILES ((Tdim + VALID - 1) / VALID)   // 8
#define SPAD (WC + 1)         // smem row pad

__global__ void __launch_bounds__(32 * WC, 4)
cml_kernel(const float* __restrict__ drive,
           const float* __restrict__ r,
           const float* __restrict__ eps,
           const float* __restrict__ beta,
           const float* __restrict__ Kc,
           float* __restrict__ out)
{
    __shared__ float st[TILE][SPAD];   // transpose staging: [time][channel]

    const int tid  = threadIdx.x;
    const int lane = tid & 31;
    const int w    = tid >> 5;               // warp = channel within block
    const int c0   = blockIdx.y * WC;
    const int cg   = c0 + w;                 // this warp's global channel
    const int b    = blockIdx.z;
    const int gt0  = (int)blockIdx.x * VALID - HALO;
    const int base = b * (Tdim * Cdim);

    // ---- stage: coalesced global -> smem [t][c] ----
#pragma unroll
    for (int it = 0; it < TILE * WC / (32 * WC); it++) {
        const int idx = it * (32 * WC) + tid;
        const int t = idx / WC;
        const int c = idx % WC;
        const int gt = gt0 + t;
        float d = 0.0f;
        if (gt >= 0 && gt < Tdim)
            d = drive[base + gt * Cdim + c0 + c];
        st[t][c] = d;
    }

    // per-channel (warp-uniform) constants; fold r into conv weights
    const float rr = r[cg];
    const float ee = eps[cg];
    const float bb = beta[cg];
    const float k0 = Kc[cg * 4 + 0];
    const float k1 = Kc[cg * 4 + 1];
    const float k2 = Kc[cg * 4 + 2];
    const float k3 = Kc[cg * 4 + 3];
    const float onemb = 1.0f - bb;
    const float A  = onemb * (1.0f - ee);
    const float Bc = onemb * ee;
    const float v3 = fmaf(Bc, k3, A) * rr;   // coeff of m'[t]
    const float v2 = Bc * k2 * rr;           // m'[t-1]
    const float v1 = Bc * k1 * rr;           // m'[t-2]
    const float v0 = Bc * k0 * rr;           // m'[t-3]

    __syncthreads();

    // ---- smem -> registers (lane-major time) ----
    float g[LL], D[LL];
#pragma unroll
    for (int i = 0; i < LL; i++) {
        const float d = st[lane * LL + i][w];
        g[i] = d;
        D[i] = bb * d;
    }

    // ---- 16 fused steps; warp-synchronous halo via shfl ----
#pragma unroll 1
    for (int step = 0; step < NSTEPS; step++) {
        // m' of this lane's last 3 cells (current-step values)
        const float gA = g[LL - 3], gB = g[LL - 2], gC = g[LL - 1];
        const float mA = fmaf(-gA, gA, gA);
        const float mB = fmaf(-gB, gB, gB);
        const float mC = fmaf(-gC, gC, gC);
        float m1 = __shfl_up_sync(0xffffffffu, mC, 1);
        float m2 = __shfl_up_sync(0xffffffffu, mB, 1);
        float m3 = __shfl_up_sync(0xffffffffu, mA, 1);
        if (lane == 0) { m1 = 0.0f; m2 = 0.0f; m3 = 0.0f; }

#pragma unroll
        for (int i = 0; i < LL; i++) {
            const float gi = g[i];
            // reuse precomputed m' for the last 3 cells
            const float m0 = (i < LL - 3) ? fmaf(-gi, gi, gi)
                           : (i == LL - 3 ? mA : (i == LL - 2 ? mB : mC));
            float acc = fmaf(v3, m0, D[i]);
            acc = fmaf(v2, m1, acc);
            acc = fmaf(v1, m2, acc);
            g[i] = fmaf(v0, m3, acc);
            m3 = m2; m2 = m1; m1 = m0;
        }
    }

    // ---- registers -> smem (clipped) ----
    __syncthreads();   // all staging reads done before rewrite
#pragma unroll
    for (int i = 0; i < LL; i++)
        st[lane * LL + i][w] = fminf(fmaxf(g[i], 1.0e-4f), 1.0f - 1.0e-4f);
    __syncthreads();

    // ---- smem -> global, coalesced-ish, skip halo ----
#pragma unroll
    for (int it = 0; it < TILE * WC / (32 * WC); it++) {
        const int idx = it * (32 * WC) + tid;
        const int t = idx / WC;
        const int c = idx % WC;
        const int gt = gt0 + t;
        if (t >= HALO && gt < Tdim)
            out[base + gt * Cdim + c0 + c] = st[t][c];
    }
}

extern "C" void kernel_launch(void* const* d_in, const int* in_sizes, int n_in,
                              void* d_out, int out_size)
{
    const float* drive = (const float*)d_in[0];
    const float* r     = (const float*)d_in[1];
    const float* eps   = (const float*)d_in[2];
    const float* beta  = (const float*)d_in[3];
    const float* Kc    = (const float*)d_in[4];
    float* out = (float*)d_out;

    dim3 grid(NTILES, Cdim / WC, Bdim);   // 8 x 64 x 4 = 2048 CTAs
    cml_kernel<<<grid, 32 * WC>>>(drive, r, eps, beta, Kc, out);
}